// round 8
// baseline (speedup 1.0000x reference)
#include <cuda_runtime.h>
#include <cuda_fp16.h>
#include <cstdint>

// ============================================================================
// MQA_22436909154690 on GB300 (sm_103 base PTX target -> HMMA mma.sync path).
//
// Math: softmax over singleton axis == 1, so
//   out[b,l] = tile(v[b,l], H),  v = x @ Wv^T + bv,  Wv = Wkv[HD:2HD, :]
// => one GEMM [16384 x 2048] @ [2048 x 128] + bias + broadcast-x16 epilogue.
//
// R8: R2-R7 all pinned at ~60us: x flowed through registers (LDG->cvt->STS),
// forcing ~1-stage prefetch distance -> raw DRAM latency exposed every chunk.
// Now: ONE loader warp cp.asyncs BOTH x (raw fp32) and B (fp16) into a 3-deep
// slot ring (no register destination -> 3 stages of latency slack). Consumers
// convert A fragments fp32->fp16 in registers (LDS.64 + cvt) feeding HMMA.
// ============================================================================

static constexpr int KDIM  = 2048;
static constexpr int MTILE = 64;
static constexpr int KC    = 64;
static constexpr int NCH   = KDIM / KC;       // 32 stages
static constexpr int NSLOT = 3;

// Slot = X fp32 [64][68] (17408 B) + B fp16 [128][72] (18432 B)
static constexpr int XROWB  = 272;            // x row stride bytes (68 floats)
static constexpr int SLOT_B = 17408;
static constexpr int STAGE  = 35840;
static constexpr int BARS   = NSLOT * STAGE;  // 107520
static constexpr int SMEM_TOTAL = BARS + 64;  // 107584 (x2 CTAs ~= 215 KB/SM)
static constexpr int V_STRIDE = 132;          // epilogue overlay

// Pre-converted Wv fp16, chunk-major: [chunk32][n=128][k=64]
__device__ __align__(16) __half g_Wh[KDIM * 128];

// ---------------------------------------------------------------------------
__device__ __forceinline__ uint32_t smem_u32(const void* p) {
    uint32_t a;
    asm("{ .reg .u64 t; cvta.to.shared.u64 t, %1; cvt.u32.u64 %0, t; }" : "=r"(a) : "l"(p));
    return a;
}
__device__ __forceinline__ void ldsm4(uint32_t* r, uint32_t addr) {
    asm volatile("ldmatrix.sync.aligned.m8n8.x4.shared.b16 {%0,%1,%2,%3}, [%4];"
                 : "=r"(r[0]), "=r"(r[1]), "=r"(r[2]), "=r"(r[3]) : "r"(addr));
}
__device__ __forceinline__ void hmma(float* d, const uint32_t* a, uint32_t b0, uint32_t b1) {
    asm volatile("mma.sync.aligned.m16n8k16.row.col.f32.f16.f16.f32 "
                 "{%0,%1,%2,%3}, {%4,%5,%6,%7}, {%8,%9}, {%0,%1,%2,%3};"
                 : "+f"(d[0]), "+f"(d[1]), "+f"(d[2]), "+f"(d[3])
                 : "r"(a[0]), "r"(a[1]), "r"(a[2]), "r"(a[3]), "r"(b0), "r"(b1));
}
__device__ __forceinline__ void cpa16(uint32_t dst, const void* src) {
    asm volatile("cp.async.cg.shared.global [%0], [%1], 16;" :: "r"(dst), "l"(src) : "memory");
}
__device__ __forceinline__ void mbar_init(uint32_t bar, uint32_t cnt) {
    asm volatile("mbarrier.init.shared.b64 [%0], %1;" :: "r"(bar), "r"(cnt) : "memory");
}
__device__ __forceinline__ void mbar_arrive(uint32_t bar) {
    asm volatile("mbarrier.arrive.shared.b64 _, [%0];" :: "r"(bar) : "memory");
}
__device__ __forceinline__ void mbar_arrive_cpasync(uint32_t bar) {
    asm volatile("cp.async.mbarrier.arrive.noinc.shared.b64 [%0];" :: "r"(bar) : "memory");
}
__device__ __forceinline__ void mbar_wait(uint32_t bar, uint32_t parity) {
    asm volatile(
        "{\n\t.reg .pred P;\n\t"
        "W%=:\n\t"
        "mbarrier.try_wait.parity.shared.b64 P, [%0], %1, 0x989680;\n\t"
        "@!P bra W%=;\n\t}"
        :: "r"(bar), "r"(parity) : "memory");
}
__device__ __forceinline__ uint32_t h2u(__half2 h) { return *reinterpret_cast<uint32_t*>(&h); }

// ---------------------------------------------------------------------------
// Pre-kernel: Wv = Wkv rows 128..255 -> fp16, chunk-major [c][n][k64].
// ---------------------------------------------------------------------------
__global__ void convert_w_kernel(const float* __restrict__ Wkv) {
    int idx = blockIdx.x * blockDim.x + threadIdx.x;  // 65536 units of 4 halves
    int h4 = idx << 2;
    int c  = h4 >> 13;
    int n  = (h4 >> 6) & 127;
    int k4 = h4 & 63;
    float4 w = *(const float4*)(Wkv + (size_t)(128 + n) * KDIM + c * KC + k4);
    __half2 p0 = __float22half2_rn(make_float2(w.x, w.y));
    __half2 p1 = __float22half2_rn(make_float2(w.z, w.w));
    *(uint2*)(g_Wh + h4) = make_uint2(h2u(p0), h2u(p1));
}

// ---------------------------------------------------------------------------
// 256 CTAs x 288 threads (8 consumer warps + 1 loader warp), 2 CTAs/SM.
// ---------------------------------------------------------------------------
__global__ void __launch_bounds__(288, 2)
mqa_gemm_kernel(const float* __restrict__ x, const float* __restrict__ bkv,
                float* __restrict__ out) {
    extern __shared__ char smem[];
    const uint32_t sb = smem_u32(smem);
    const int tid  = threadIdx.x;
    const int wid  = tid >> 5;
    const int lane = tid & 31;

    const float* xb = x + (size_t)blockIdx.x * MTILE * KDIM;

    if (tid == 0) {
        #pragma unroll
        for (int i = 0; i < NSLOT; ++i) {
            mbar_init(sb + BARS + i * 16,     32);   // full: 32 loader-lane async arrives
            mbar_init(sb + BARS + i * 16 + 8, 256);  // empty: 256 consumer arrives
        }
    }
    __syncthreads();

    float acc[2][4][4];
    const int warp_m = wid >> 2;     // valid for wid 0..7
    const int warp_n = wid & 3;

    if (wid == 8) {
        // ================= LOADER: 1 warp =================
        int slot = 0, phase = 0;
        for (int s = 0; s < NCH; ++s) {
            const uint32_t full  = sb + BARS + slot * 16;
            const uint32_t empty = full + 8;
            mbar_wait(empty, phase ^ 1);             // fresh barrier: parity 1 passes

            const uint32_t xbase = sb + slot * STAGE;
            #pragma unroll
            for (int j = 0; j < 32; ++j) {           // x: 16 KB fp32
                int u = lane + j * 32;               // 16B unit: row = u>>4, c16 = u&15
                cpa16(xbase + (u >> 4) * XROWB + ((u & 15) << 4),
                      xb + (size_t)(u >> 4) * KDIM + s * KC + ((u & 15) << 2));
            }
            const __half* bsrc = g_Wh + (size_t)s * (128 * KC);
            const uint32_t bbase = xbase + SLOT_B;
            #pragma unroll
            for (int j = 0; j < 32; ++j) {           // B: 16 KB fp16
                int u = lane + j * 32;               // n = u>>3, seg = u&7
                cpa16(bbase + (u >> 3) * 144 + ((u & 7) << 4),
                      bsrc + (u >> 3) * KC + ((u & 7) << 3));
            }
            mbar_arrive_cpasync(full);               // fires when this lane's cps land

            if (++slot == NSLOT) { slot = 0; phase ^= 1; }
        }
    } else {
        // ================= CONSUMERS: 8 warps =================
        // A fragments read as fp32 pairs from the x slot, converted in regs.
        // m16n8k16 A layout: reg r holds rows (lane>>2)+{0,8}, cols 2*(lane&3)+{0,8}.
        const uint32_t aRel = (uint32_t)(warp_m * 32 + (lane >> 2)) * XROWB
                            + ((lane & 3) << 3);
        uint32_t bRel[2];
        #pragma unroll
        for (int g = 0; g < 2; ++g)
            bRel[g] = SLOT_B + (uint32_t)(warp_n * 32 + g * 16 + (lane & 15)) * 144
                    + ((lane >> 4) << 4);

        #pragma unroll
        for (int mf = 0; mf < 2; ++mf)
            #pragma unroll
            for (int nf = 0; nf < 4; ++nf)
                #pragma unroll
                for (int r = 0; r < 4; ++r) acc[mf][nf][r] = 0.f;

        int slot = 0, phase = 0;
        for (int s = 0; s < NCH; ++s) {
            const uint32_t full  = sb + BARS + slot * 16;
            const uint32_t empty = full + 8;
            mbar_wait(full, phase);

            const uint32_t stg = sb + slot * STAGE;
            const char* ab = smem + (stg - sb) + aRel;   // generic pointer for LDS
            #pragma unroll
            for (int kk = 0; kk < 4; ++kk) {
                uint32_t b[2][4];
                ldsm4(b[0], stg + bRel[0] + kk * 32);
                ldsm4(b[1], stg + bRel[1] + kk * 32);
                #pragma unroll
                for (int mf = 0; mf < 2; ++mf) {
                    const char* p = ab + mf * (16 * XROWB) + kk * 64;
                    float2 v0 = *(const float2*)(p);                    // (r, c)
                    float2 v1 = *(const float2*)(p + 8 * XROWB);        // (r+8, c)
                    float2 v2 = *(const float2*)(p + 32);               // (r, c+8)
                    float2 v3 = *(const float2*)(p + 8 * XROWB + 32);   // (r+8, c+8)
                    uint32_t a[4];
                    a[0] = h2u(__floats2half2_rn(v0.x, v0.y));
                    a[1] = h2u(__floats2half2_rn(v1.x, v1.y));
                    a[2] = h2u(__floats2half2_rn(v2.x, v2.y));
                    a[3] = h2u(__floats2half2_rn(v3.x, v3.y));
                    hmma(acc[mf][0], a, b[0][0], b[0][2]);
                    hmma(acc[mf][1], a, b[0][1], b[0][3]);
                    hmma(acc[mf][2], a, b[1][0], b[1][2]);
                    hmma(acc[mf][3], a, b[1][1], b[1][3]);
                }
            }
            mbar_arrive(empty);
            if (++slot == NSLOT) { slot = 0; phase ^= 1; }
        }
    }

    __syncthreads();   // all stages consumed; slot memory free for overlay

    // --- epilogue: consumers add bias and stage v tile in SMEM ---
    float* vsm = (float*)smem;
    if (tid < 256) {
        float bias[4][2];
        {
            int c0 = warp_n * 32 + (lane & 3) * 2;
            #pragma unroll
            for (int nf = 0; nf < 4; ++nf) {
                bias[nf][0] = bkv[128 + c0 + nf * 8];
                bias[nf][1] = bkv[129 + c0 + nf * 8];
            }
        }
        int r0 = warp_m * 32 + (lane >> 2);
        #pragma unroll
        for (int mf = 0; mf < 2; ++mf) {
            #pragma unroll
            for (int nf = 0; nf < 4; ++nf) {
                int r = r0 + mf * 16;
                int c = warp_n * 32 + nf * 8 + (lane & 3) * 2;
                vsm[r * V_STRIDE + c]           = acc[mf][nf][0] + bias[nf][0];
                vsm[r * V_STRIDE + c + 1]       = acc[mf][nf][1] + bias[nf][1];
                vsm[(r + 8) * V_STRIDE + c]     = acc[mf][nf][2] + bias[nf][0];
                vsm[(r + 8) * V_STRIDE + c + 1] = acc[mf][nf][3] + bias[nf][1];
            }
        }
    }
    __syncthreads();

    // Broadcast: all 9 warps; each v row written 16x (one per head), coalesced.
    float* ob = out + (size_t)blockIdx.x * MTILE * 2048;
    for (int r = wid; r < MTILE; r += 9) {
        float4 val = *(const float4*)(vsm + r * V_STRIDE + lane * 4);
        float4* orow = (float4*)(ob + (size_t)r * 2048);
        #pragma unroll
        for (int h = 0; h < 16; ++h) orow[lane + h * 32] = val;
    }
}

// ---------------------------------------------------------------------------
extern "C" void kernel_launch(void* const* d_in, const int* in_sizes, int n_in,
                              void* d_out, int out_size) {
    const float* x   = (const float*)d_in[0];   // (4,4096,2048) fp32
    const float* Wkv = (const float*)d_in[3];   // (256,2048) fp32
    const float* bkv = (const float*)d_in[4];   // (256,) fp32
    float* out = (float*)d_out;                 // (4,4096,2048) fp32

    cudaFuncSetAttribute(mqa_gemm_kernel,
                         cudaFuncAttributeMaxDynamicSharedMemorySize, SMEM_TOTAL);

    convert_w_kernel<<<256, 256>>>(Wkv);
    mqa_gemm_kernel<<<16384 / MTILE, 288, SMEM_TOTAL>>>(x, bkv, out);
}